// round 17
// baseline (speedup 1.0000x reference)
#include <cuda_runtime.h>
#include <cuda_fp16.h>
#include <cstdint>

#define B_ 2
#define S_ 8192
#define D_ 128
#define BM 64
#define BN 64
#define TITER 128
#define NTHREADS 256

#define QSCALE (0.08838834764831843f * 1.4426950408889634f)

#define KROWB 272
#define VROWB 144
#define PROWB 144

// ---- smem byte layout ----
#define SM_KH0 0
#define SM_KH1 17408
#define SM_VP0 34816
#define SM_VP1 53248
#define SM_PP  71680          // 64 rows * 144B
#define SM_LS  80896          // 128 floats
#define SMEM_BYTES 81408

#define ONES2 0x3C003C00u

__device__ __half   g_Kh[B_ * S_ * D_];
__device__ uint32_t g_VpT[B_ * D_ * (S_ / 2)];

__device__ __forceinline__ uint32_t smem_u32(const void* p) {
    uint32_t a;
    asm("{ .reg .u64 t; cvta.to.shared.u64 t, %1; cvt.u32.u64 %0, t; }" : "=r"(a) : "l"(p));
    return a;
}
__device__ __forceinline__ uint32_t packh2(float lo, float hi) {
    __half2 h = __floats2half2_rn(lo, hi);
    return *reinterpret_cast<uint32_t*>(&h);
}
#define CP_ASYNC16(s, g) asm volatile("cp.async.cg.shared.global [%0], [%1], 16;" :: "r"(s), "l"(g) : "memory")
#define CP_COMMIT()      asm volatile("cp.async.commit_group;" ::: "memory")
#define CP_WAIT0()       asm volatile("cp.async.wait_group 0;" ::: "memory")

#define LDSM_X4(d0, d1, d2, d3, a) asm volatile( \
    "ldmatrix.sync.aligned.m8n8.x4.shared.b16 {%0,%1,%2,%3}, [%4];" \
    : "=r"(d0), "=r"(d1), "=r"(d2), "=r"(d3) : "r"(a))

__device__ __forceinline__ void mma16(float* c, const uint32_t* a, uint32_t b0, uint32_t b1) {
    asm volatile(
        "mma.sync.aligned.m16n8k16.row.col.f32.f16.f16.f32 "
        "{%0,%1,%2,%3}, {%4,%5,%6,%7}, {%8,%9}, {%0,%1,%2,%3};"
        : "+f"(c[0]), "+f"(c[1]), "+f"(c[2]), "+f"(c[3])
        : "r"(a[0]), "r"(a[1]), "r"(a[2]), "r"(a[3]), "r"(b0), "r"(b1));
}

// ================= merged pre-pass =================
__global__ void prep_kernel(const float* __restrict__ K, const float* __restrict__ V) {
    if (blockIdx.x < 256) {
        __shared__ float raw[64 * 132];
        const int kb    = blockIdx.x;
        const int batch = kb >> 7;
        const int key0  = (kb & 127) * 64;
        const int tid   = threadIdx.x;

        const float* Vb = V + ((size_t)batch * S_ + key0) * D_;
        for (int i = tid; i < 64 * 32; i += 256) {
            int r = i >> 5, c = (i & 31) << 2;
            *reinterpret_cast<float4*>(raw + r * 132 + c) =
                *reinterpret_cast<const float4*>(Vb + r * D_ + c);
        }
        __syncthreads();

        const int d  = tid >> 1;
        const int hf = tid & 1;
        uint32_t* dst = g_VpT + (size_t)batch * D_ * (S_ / 2) + (size_t)d * (S_ / 2) + (key0 >> 1);
        #pragma unroll
        for (int i = 0; i < 4; ++i) {
            int rp = 16 * hf + 4 * i;
            uint4 o;
            o.x = packh2(raw[(2 * rp)     * 132 + d], raw[(2 * rp + 1) * 132 + d]);
            o.y = packh2(raw[(2 * rp + 2) * 132 + d], raw[(2 * rp + 3) * 132 + d]);
            o.z = packh2(raw[(2 * rp + 4) * 132 + d], raw[(2 * rp + 5) * 132 + d]);
            o.w = packh2(raw[(2 * rp + 6) * 132 + d], raw[(2 * rp + 7) * 132 + d]);
            *reinterpret_cast<uint4*>(dst + rp) = o;
        }
    } else {
        const int n = B_ * S_ * D_ / 4;
        for (int i = (blockIdx.x - 256) * blockDim.x + threadIdx.x; i < n;
             i += 1024 * blockDim.x) {
            float4 f = reinterpret_cast<const float4*>(K)[i];
            reinterpret_cast<uint2*>(g_Kh)[i] = make_uint2(packh2(f.x, f.y), packh2(f.z, f.w));
        }
    }
}

// ================= main kernel =================
__global__ void __launch_bounds__(NTHREADS, 2)
attn_fp16_kernel(const float* __restrict__ Q, float* __restrict__ Out)
{
    extern __shared__ char smem[];
    const uint32_t smem_base = smem_u32(smem);

    const int tid  = threadIdx.x;
    const int warp = tid >> 5;
    const int wm   = warp >> 1;     // 0..3 : m-slice, rows 16*wm..+16
    const int wn   = warp & 1;      // 0..1 : key half (QK) / d half (PV)
    const int lane = tid & 31;
    const int g    = lane >> 2;
    const int tg   = lane & 3;
    const int mrow = wm * 16;

    const int qt = blockIdx.x;
    const int bb = blockIdx.y;

    const float* Qb = Q + ((size_t)bb * S_ + (size_t)qt * BM) * D_;
    const char*  gK = (const char*)(g_Kh + (size_t)bb * S_ * D_);
    const char*  gV = (const char*)(g_VpT + (size_t)bb * D_ * (S_ / 2));

    uint32_t* sPp = (uint32_t*)(smem + SM_PP);
    float*    ls  = (float*)(smem + SM_LS);

    // LDSM lane-address offsets
    const uint32_t kRowOff = (uint32_t)((32 * wn + (lane & 7) + ((lane >> 4) << 3)) * KROWB
                                        + ((lane >> 3) & 1) * 16);
    const uint32_t vRowOff = (uint32_t)((64 * wn + (lane & 7) + ((lane >> 4) << 3)) * VROWB
                                        + ((lane >> 3) & 1) * 16);
    const uint32_t pRowOff = (uint32_t)(((lane & 7) + ((lane >> 3) & 1) * 8) * PROWB
                                        + ((lane >> 4) & 1) * 16);

    // ---- Q fragments (one-time, from gmem): m16, all of D ----
    uint32_t qf[8][4];
    {
        const float* q0 = Qb + (mrow + g) * D_;
        const float* q1 = q0 + 8 * D_;
        #pragma unroll
        for (int jk = 0; jk < 8; ++jk) {
            float2 a = *reinterpret_cast<const float2*>(q0 + 16 * jk + 2 * tg);
            float2 b = *reinterpret_cast<const float2*>(q1 + 16 * jk + 2 * tg);
            float2 c = *reinterpret_cast<const float2*>(q0 + 16 * jk + 2 * tg + 8);
            float2 d = *reinterpret_cast<const float2*>(q1 + 16 * jk + 2 * tg + 8);
            qf[jk][0] = packh2(a.x * QSCALE, a.y * QSCALE);
            qf[jk][1] = packh2(b.x * QSCALE, b.y * QSCALE);
            qf[jk][2] = packh2(c.x * QSCALE, c.y * QSCALE);
            qf[jk][3] = packh2(d.x * QSCALE, d.y * QSCALE);
        }
    }

    // ---- tile stager (256 threads) ----
    auto stage = [&](int t, int buf) {
        const char* kp = gK + (size_t)t * BN * D_ * 2;
        const char* vp = gV + (size_t)t * (BN / 2) * 4;
        uint32_t sK = smem_base + (buf ? SM_KH1 : SM_KH0);
        uint32_t sV = smem_base + (buf ? SM_VP1 : SM_VP0);
        #pragma unroll
        for (int k = 0; k < 4; ++k) {
            int id = tid + NTHREADS * k;
            int kr = id >> 4, kc = id & 15;
            CP_ASYNC16(sK + kr * KROWB + kc * 16, kp + kr * 256 + kc * 16);
            int vr = id >> 3, vc = id & 7;
            CP_ASYNC16(sV + vr * VROWB + vc * 16, vp + (size_t)vr * (S_ * 2) + vc * 16);
        }
        CP_COMMIT();
    };

    stage(0, 0);

    float of[8][4];
    #pragma unroll
    for (int j = 0; j < 8; ++j)
        #pragma unroll
        for (int e = 0; e < 4; ++e) of[j][e] = 0.0f;
    float lacc[4] = {0.0f, 0.0f, 0.0f, 0.0f};

    CP_WAIT0();
    __syncthreads();

    for (int t = 0; t < TITER; ++t) {
        const int cur = t & 1;
        const bool more = (t + 1 < TITER);
        if (more) stage(t + 1, cur ^ 1);

        // ---- S = Q K^T : m16 x n32 (own key half) ----
        const uint32_t sKhA = smem_base + (cur ? SM_KH1 : SM_KH0);
        float c[4][4];
        #pragma unroll
        for (int j = 0; j < 4; ++j)
            #pragma unroll
            for (int e = 0; e < 4; ++e) c[j][e] = 0.0f;

        #pragma unroll
        for (int jk = 0; jk < 8; ++jk) {
            #pragma unroll
            for (int jnp = 0; jnp < 2; ++jnp) {
                uint32_t k0, k1, k2, k3;
                LDSM_X4(k0, k1, k2, k3, sKhA + kRowOff + jnp * (16 * KROWB) + jk * 32);
                mma16(c[2 * jnp],     qf[jk], k0, k1);
                mma16(c[2 * jnp + 1], qf[jk], k2, k3);
            }
        }

        // ---- softmax (f16x2 exp) + publish own P half + partial row sums ----
        uint32_t p2[8];
        #pragma unroll
        for (int jn = 0; jn < 4; ++jn) {
            uint32_t a = packh2(c[jn][0], c[jn][1]);
            uint32_t b = packh2(c[jn][2], c[jn][3]);
            asm("ex2.approx.f16x2 %0, %0;" : "+r"(a));
            asm("ex2.approx.f16x2 %0, %0;" : "+r"(b));
            p2[2 * jn]     = a;
            p2[2 * jn + 1] = b;
            int pc = 16 * wn + 4 * jn + tg;
            sPp[(mrow + g)     * 36 + pc] = a;
            sPp[(mrow + g + 8) * 36 + pc] = b;
        }
        mma16(lacc, &p2[0], ONES2, ONES2);
        mma16(lacc, &p2[4], ONES2, ONES2);

        __syncthreads();   // P tile complete

        // ---- O += P V : m16 x d64 (own d half, all 64 keys) ----
        const uint32_t sVA  = smem_base + (cur ? SM_VP1 : SM_VP0);
        const uint32_t sPpA = smem_base + SM_PP;
        #pragma unroll
        for (int jkb = 0; jkb < 4; ++jkb) {
            uint32_t pa[4];
            if ((jkb >> 1) == wn) {          // own key block: from exp registers
                const int j = jkb & 1;
                pa[0] = p2[4 * j];
                pa[1] = p2[4 * j + 1];
                pa[2] = p2[4 * j + 2];
                pa[3] = p2[4 * j + 3];
            } else {                         // partner key block: LDSM from smem
                LDSM_X4(pa[0], pa[1], pa[2], pa[3],
                        sPpA + mrow * PROWB + pRowOff + 32 * jkb);
            }
            #pragma unroll
            for (int jnp = 0; jnp < 4; ++jnp) {
                uint32_t v0, v1, v2, v3;
                LDSM_X4(v0, v1, v2, v3, sVA + vRowOff + jnp * (16 * VROWB) + jkb * 32);
                mma16(of[2 * jnp],     pa, v0, v1);
                mma16(of[2 * jnp + 1], pa, v2, v3);
            }
        }

        if (more) CP_WAIT0();
        __syncthreads();   // P reusable; next K/V landed
    }

    // ================= epilogue =================
    // lacc holds row sums over own n32 half; combine across wn pairs.
    if (tg == 0) {
        ls[wn * 64 + mrow + g]     = lacc[0];   // row g sum (D-frag order)
        ls[wn * 64 + mrow + g + 8] = lacc[2];   // row g+8 sum
    }
    __syncthreads();

    float* Ob = Out + ((size_t)bb * S_ + (size_t)qt * BM) * D_;
    const int row = mrow + g;
    const float inv0 = 1.0f / (ls[row] + ls[64 + row]);
    const float inv1 = 1.0f / (ls[row + 8] + ls[64 + row + 8]);
    float* r0 = Ob + row * D_ + 64 * wn;
    float* r1 = Ob + (row + 8) * D_ + 64 * wn;
    #pragma unroll
    for (int jn = 0; jn < 8; ++jn) {
        *reinterpret_cast<float2*>(r0 + 8 * jn + 2 * tg) =
            make_float2(of[jn][0] * inv0, of[jn][1] * inv0);
        *reinterpret_cast<float2*>(r1 + 8 * jn + 2 * tg) =
            make_float2(of[jn][2] * inv1, of[jn][3] * inv1);
    }
}

extern "C" void kernel_launch(void* const* d_in, const int* in_sizes, int n_in,
                              void* d_out, int out_size)
{
    const float* Q = (const float*)d_in[0];
    const float* K = (const float*)d_in[1];
    const float* V = (const float*)d_in[2];
    float* O = (float*)d_out;

    prep_kernel<<<1280, 256>>>(K, V);

    cudaFuncSetAttribute(attn_fp16_kernel,
                         cudaFuncAttributeMaxDynamicSharedMemorySize, SMEM_BYTES);

    dim3 grid(S_ / BM, B_);
    attn_fp16_kernel<<<grid, NTHREADS, SMEM_BYTES>>>(Q, O);
}